// round 6
// baseline (speedup 1.0000x reference)
#include <cuda_runtime.h>
#include <cuda_bf16.h>
#include <math.h>
#include <stdint.h>

// ---------------- problem constants ----------------
#define BB 8
#define SS 4096
#define EE 1024
#define SD 8
#define MM (BB*SS)          // 32768
#define LDIN 1032           // E + SD
#define NITER 32            // K=1024 / 32

// ================= portable PTX helpers (sm_80+) =================
__device__ __forceinline__ uint32_t smem_to_u32(const void* smem_ptr) {
    uint32_t addr;
    asm("{ .reg .u64 tmp; cvta.to.shared.u64 tmp, %1; cvt.u32.u64 %0, tmp; }"
        : "=r"(addr) : "l"(smem_ptr));
    return addr;
}

#define CP_ASYNC16(dst, src) \
    asm volatile("cp.async.cg.shared.global [%0], [%1], 16;" \
                 :: "r"(dst), "l"(src) : "memory")
#define CP_COMMIT() asm volatile("cp.async.commit_group;" ::: "memory")
#define CP_WAIT2()  asm volatile("cp.async.wait_group 2;"  ::: "memory")

__device__ __forceinline__ void ldsm_x4(uint32_t& r0, uint32_t& r1,
                                        uint32_t& r2, uint32_t& r3,
                                        uint32_t addr) {
    asm volatile("ldmatrix.sync.aligned.m8n8.x4.shared.b16 {%0,%1,%2,%3}, [%4];"
                 : "=r"(r0), "=r"(r1), "=r"(r2), "=r"(r3) : "r"(addr));
}

__device__ __forceinline__ void mma16816(float* d, const uint32_t* a,
                                         const uint32_t* b) {
    asm volatile("mma.sync.aligned.m16n8k16.row.col.f32.bf16.bf16.f32 "
                 "{%0,%1,%2,%3}, {%4,%5,%6,%7}, {%8,%9}, {%0,%1,%2,%3};"
                 : "+f"(d[0]), "+f"(d[1]), "+f"(d[2]), "+f"(d[3])
                 : "r"(a[0]), "r"(a[1]), "r"(a[2]), "r"(a[3]),
                   "r"(b[0]), "r"(b[1]));
}

// ---------------- scratch (device globals, no allocs) ----------------
__device__ float g_Weff[EE * EE];
__device__ float g_Wg_eff[EE * SD];
__device__ float g_bg_eff[SD];
__device__ float g_bout_eff[EE];
__device__ float g_gate[MM * SD];
__device__ float g_si[MM * SD];
__device__ float g_states[MM * SD];
__device__ __nv_bfloat16 g_XHi[(size_t)MM * EE];     // 64 MB
__device__ __nv_bfloat16 g_XLo[(size_t)MM * EE];     // 64 MB
__device__ __nv_bfloat16 g_WinHi[(size_t)EE * EE];
__device__ __nv_bfloat16 g_WinLo[(size_t)EE * EE];
__device__ __nv_bfloat16 g_WoutHi[(size_t)EE * EE];  // transposed
__device__ __nv_bfloat16 g_WoutLo[(size_t)EE * EE];
__device__ __nv_bfloat16 g_BweffHi[(size_t)EE * EE]; // transposed
__device__ __nv_bfloat16 g_BweffLo[(size_t)EE * EE];

// ---------------- precompute small folded weights ----------------
__global__ void precompute_kernel(const float* __restrict__ W_in,
                                  const float* __restrict__ W_g,
                                  const float* __restrict__ b_g,
                                  const float* __restrict__ b_in,
                                  const float* __restrict__ W_out,
                                  const float* __restrict__ b_out,
                                  float* __restrict__ Wg_eff,
                                  float* __restrict__ bg_eff,
                                  float* __restrict__ bout_eff)
{
    int gid = blockIdx.x * blockDim.x + threadIdx.x;
    if (gid < EE * SD) {
        int e = gid >> 3, d = gid & 7;
        float s = 0.f;
        const float* wr = W_in + (size_t)e * LDIN;
        #pragma unroll 4
        for (int c = 0; c < LDIN; c++) s = fmaf(wr[c], W_g[c * SD + d], s);
        Wg_eff[e * SD + d] = s;
    } else if (gid < EE * SD + SD) {
        int d = gid - EE * SD;
        float s = b_g[d];
        for (int c = 0; c < LDIN; c++) s = fmaf(b_in[c], W_g[c * SD + d], s);
        bg_eff[d] = s;
    } else if (gid < EE * SD + SD + EE) {
        int n = gid - (EE * SD + SD);
        float s = b_out[n];
        for (int c = 0; c < EE; c++) s = fmaf(b_in[c], W_out[(size_t)c * EE + n], s);
        bout_eff[n] = s;
    }
}

// ---------------- hi/lo bf16 decomposition, row-major source ----------------
__global__ void decompose_rows_kernel(const float* __restrict__ src, int srcld,
                                      __nv_bfloat16* __restrict__ Hi,
                                      __nv_bfloat16* __restrict__ Lo)
{
    int r = blockIdx.x;
    int c4 = threadIdx.x * 4;
    float4 v = *(const float4*)(src + (size_t)r * srcld + c4);
    struct alignas(8) B4 { __nv_bfloat16 b[4]; };
    B4 H, L;
    float vv[4] = {v.x, v.y, v.z, v.w};
    #pragma unroll
    for (int i = 0; i < 4; i++) {
        __nv_bfloat16 h = __float2bfloat16(vv[i]);
        H.b[i] = h;
        L.b[i] = __float2bfloat16(vv[i] - __bfloat162float(h));
    }
    *(B4*)(Hi + (size_t)r * EE + c4) = H;
    *(B4*)(Lo + (size_t)r * EE + c4) = L;
}

// ---------------- hi/lo bf16 decomposition, transposed source -------------
__global__ void decompose_trans_kernel(const float* __restrict__ src,
                                       __nv_bfloat16* __restrict__ Hi,
                                       __nv_bfloat16* __restrict__ Lo)
{
    __shared__ float tile[32][33];
    int e0 = blockIdx.x * 32, n0 = blockIdx.y * 32;
    int tx = threadIdx.x, ty = threadIdx.y;     // 32 x 8
    #pragma unroll
    for (int i = 0; i < 4; i++)
        tile[ty + i * 8][tx] = src[(size_t)(e0 + ty + i * 8) * 1024 + n0 + tx];
    __syncthreads();
    #pragma unroll
    for (int i = 0; i < 4; i++) {
        int n = n0 + ty + i * 8;
        float v = tile[tx][ty + i * 8];
        __nv_bfloat16 h = __float2bfloat16(v);
        __nv_bfloat16 l = __float2bfloat16(v - __bfloat162float(h));
        Hi[(size_t)n * EE + e0 + tx] = h;
        Lo[(size_t)n * EE + e0 + tx] = l;
    }
}

// ================= warp-mma split-bf16 GEMM =================
// C[m][n] = sum_k x[m][k]*W[k][n] computed as hi·hi + hi·lo + lo·hi over K=1024.
// A arrays: Ahi/Alo [M][1024] bf16; B arrays: Bhi/Blo [1024 n-rows][1024] bf16.
// CTA 128x128, K-chunk 32, 3-stage cp.async pipeline, 8 warps (64x32 tiles).
// SMEM row (128B) packs [hi 64B | lo 64B] per matrix row; 128B XOR swizzle.
// Optional epilogue: C += bias[n] + Srank[m][.]·Wbot[.][n] (Wbot ld 1024).
__global__ void __launch_bounds__(256, 2)
gemm_mma_kernel(const __nv_bfloat16* __restrict__ Ahi,
                const __nv_bfloat16* __restrict__ Alo,
                const __nv_bfloat16* __restrict__ Bhi,
                const __nv_bfloat16* __restrict__ Blo,
                float* __restrict__ C,
                const float* __restrict__ bias,
                const float* __restrict__ Srank,
                const float* __restrict__ Wbot)
{
    extern __shared__ char smem[];               // 3 stages x (A 16KB + B 16KB)
    const uint32_t sb = smem_to_u32(smem);
    const int tid  = threadIdx.x;
    const int lane = tid & 31;
    const int wid  = tid >> 5;
    const int wm   = wid >> 2;                   // 0..1
    const int wn   = wid & 3;                    // 0..3
    const int n0   = blockIdx.x * 128;
    const int m0   = blockIdx.y * 128;

    float acc[4][4][4];
    #pragma unroll
    for (int mi = 0; mi < 4; mi++)
        #pragma unroll
        for (int ni = 0; ni < 4; ni++)
            #pragma unroll
            for (int e = 0; e < 4; e++) acc[mi][ni][e] = 0.f;

    // per-thread fill assignment: fixed seg = tid&7, rows tid>>3 + {0,32,64,96}
    const int row0 = tid >> 3;
    const int seg  = tid & 7;
    const bool isHi = (seg < 4);
    const int kseg8 = (isHi ? seg : seg - 4) * 8;   // bf16 offset within chunk
    const __nv_bfloat16* const Asrc = (isHi ? Ahi : Alo) + kseg8;
    const __nv_bfloat16* const Bsrc = (isHi ? Bhi : Blo) + kseg8;

    auto prefetch = [&](int stage, int kb) {
        const uint32_t aOff = sb + (uint32_t)stage * 32768u;
        const uint32_t bOff = aOff + 16384u;
        #pragma unroll
        for (int i = 0; i < 4; i++) {
            int row = row0 + i * 32;
            uint32_t sw = (uint32_t)row * 128u + (uint32_t)((seg ^ (row & 7)) * 16);
            CP_ASYNC16(aOff + sw, Asrc + (size_t)(m0 + row) * EE + kb);
            CP_ASYNC16(bOff + sw, Bsrc + (size_t)(n0 + row) * EE + kb);
        }
    };

    prefetch(0, 0);  CP_COMMIT();
    prefetch(1, 32); CP_COMMIT();

    // ldmatrix per-thread row offsets (proven layout)
    const int rA  = ((lane >> 3) & 1) * 8 + (lane & 7);
    const int kA8 = lane >> 4;
    const int rB  = (lane >> 4) * 8 + (lane & 7);
    const int kB8 = (lane >> 3) & 1;

    for (int it = 0; it < NITER; it++) {
        if (it + 2 < NITER) prefetch((it + 2) % 3, (it + 2) * 32);
        CP_COMMIT();
        CP_WAIT2();
        __syncthreads();

        const uint32_t aB = sb + (uint32_t)(it % 3) * 32768u;
        const uint32_t bB = aB + 16384u;

        #pragma unroll
        for (int ks = 0; ks < 2; ks++) {
            uint32_t afh[4][4], afl[4][4], bfh[4][2], bfl[4][2];
            #pragma unroll
            for (int mi = 0; mi < 4; mi++) {
                int row = wm * 64 + mi * 16 + rA;
                int sh  = ks * 2 + kA8;            // hi seg 0..3
                ldsm_x4(afh[mi][0], afh[mi][1], afh[mi][2], afh[mi][3],
                        aB + (uint32_t)row * 128u + (uint32_t)(((sh)     ^ (row & 7)) * 16));
                ldsm_x4(afl[mi][0], afl[mi][1], afl[mi][2], afl[mi][3],
                        aB + (uint32_t)row * 128u + (uint32_t)(((sh + 4) ^ (row & 7)) * 16));
            }
            #pragma unroll
            for (int np = 0; np < 2; np++) {
                int row = wn * 32 + np * 16 + rB;
                int sh  = ks * 2 + kB8;
                uint32_t r0, r1, r2, r3;
                ldsm_x4(r0, r1, r2, r3,
                        bB + (uint32_t)row * 128u + (uint32_t)(((sh)     ^ (row & 7)) * 16));
                bfh[np * 2][0] = r0;     bfh[np * 2][1] = r1;
                bfh[np * 2 + 1][0] = r2; bfh[np * 2 + 1][1] = r3;
                ldsm_x4(r0, r1, r2, r3,
                        bB + (uint32_t)row * 128u + (uint32_t)(((sh + 4) ^ (row & 7)) * 16));
                bfl[np * 2][0] = r0;     bfl[np * 2][1] = r1;
                bfl[np * 2 + 1][0] = r2; bfl[np * 2 + 1][1] = r3;
            }
            #pragma unroll
            for (int mi = 0; mi < 4; mi++)
                #pragma unroll
                for (int ni = 0; ni < 4; ni++) {
                    mma16816(acc[mi][ni], afh[mi], bfh[ni]);   // hi·hi
                    mma16816(acc[mi][ni], afh[mi], bfl[ni]);   // hi·lo
                    mma16816(acc[mi][ni], afl[mi], bfh[ni]);   // lo·hi
                }
        }
        __syncthreads();
    }

    // ---------------- epilogue ----------------
    const bool epi = (Srank != nullptr);
    float* const sBias = (float*)smem;                 // 128 f
    float* const sSt   = (float*)(smem + 512);         // 128 x 8
    float* const sWb   = (float*)(smem + 512 + 4096);  // 8 x 128
    if (epi) {
        if (tid < 128) sBias[tid] = bias[n0 + tid];
        ((float4*)sSt)[tid] = ((const float4*)(Srank + (size_t)m0 * SD))[tid];
        for (int i = tid; i < 1024; i += 256) {
            int d8 = i >> 7, nl = i & 127;
            sWb[d8 * 128 + nl] = Wbot[(size_t)d8 * 1024 + n0 + nl];
        }
    }
    __syncthreads();

    const int lr  = lane >> 2;
    const int lc2 = (lane & 3) * 2;
    #pragma unroll
    for (int mi = 0; mi < 4; mi++) {
        int r0l = wm * 64 + mi * 16 + lr;
        int r1l = r0l + 8;
        float st0[SD], st1[SD];
        if (epi) {
            #pragma unroll
            for (int d = 0; d < SD; d++) {
                st0[d] = sSt[r0l * SD + d];
                st1[d] = sSt[r1l * SD + d];
            }
        }
        #pragma unroll
        for (int ni = 0; ni < 4; ni++) {
            int cg = wn * 32 + ni * 8 + lc2;
            float* d = acc[mi][ni];
            if (epi) {
                float s00 = sBias[cg], s01 = sBias[cg + 1];
                float s10 = s00, s11 = s01;
                #pragma unroll
                for (int dd = 0; dd < SD; dd++) {
                    float w0 = sWb[dd * 128 + cg], w1 = sWb[dd * 128 + cg + 1];
                    s00 = fmaf(st0[dd], w0, s00); s01 = fmaf(st0[dd], w1, s01);
                    s10 = fmaf(st1[dd], w0, s10); s11 = fmaf(st1[dd], w1, s11);
                }
                d[0] += s00; d[1] += s01; d[2] += s10; d[3] += s11;
            }
            float2 o0 = { d[0], d[1] };
            float2 o1 = { d[2], d[3] };
            *(float2*)(C + (size_t)(m0 + r0l) * 1024 + n0 + cg) = o0;
            *(float2*)(C + (size_t)(m0 + r1l) * 1024 + n0 + cg) = o1;
        }
    }
}

// ---------------- skinny pass: gate + state_in ----------------
__global__ __launch_bounds__(256)
void gate_si_kernel(const float* __restrict__ x,
                    const float* __restrict__ Wg_eff,
                    const float* __restrict__ W_in,
                    const float* __restrict__ bg_eff,
                    const float* __restrict__ b_in,
                    float* __restrict__ gate,
                    float* __restrict__ si)
{
    __shared__ float sWT[16][512];
    const int tid = threadIdx.x;
    const int lane = tid & 31;
    const int warp = tid >> 5;
    const int m0 = blockIdx.x * 32 + warp * 4;

    float acc[4][16];
    #pragma unroll
    for (int r = 0; r < 4; r++)
        #pragma unroll
        for (int d = 0; d < 16; d++) acc[r][d] = 0.f;

    for (int p = 0; p < 2; p++) {
        for (int idx = tid; idx < 16 * 512; idx += 256) {
            int d = idx >> 9, el = idx & 511;
            int e = p * 512 + el;
            sWT[d][el] = (d < 8) ? Wg_eff[e * SD + d]
                                 : W_in[(size_t)e * LDIN + EE + (d - 8)];
        }
        __syncthreads();

        for (int eb = 0; eb < 512; eb += 32) {
            float xv[4];
            #pragma unroll
            for (int r = 0; r < 4; r++)
                xv[r] = x[(size_t)(m0 + r) * EE + p * 512 + eb + lane];
            #pragma unroll
            for (int d = 0; d < 16; d++) {
                float w = sWT[d][eb + lane];
                #pragma unroll
                for (int r = 0; r < 4; r++)
                    acc[r][d] = fmaf(xv[r], w, acc[r][d]);
            }
        }
        __syncthreads();
    }

    #pragma unroll
    for (int r = 0; r < 4; r++) {
        #pragma unroll
        for (int d = 0; d < 16; d++) {
            float v = acc[r][d];
            v += __shfl_xor_sync(0xffffffffu, v, 16);
            v += __shfl_xor_sync(0xffffffffu, v, 8);
            v += __shfl_xor_sync(0xffffffffu, v, 4);
            v += __shfl_xor_sync(0xffffffffu, v, 2);
            v += __shfl_xor_sync(0xffffffffu, v, 1);
            acc[r][d] = v;
        }
        int m = m0 + r;
        if (lane < 8) {
            float logit = acc[r][lane] + bg_eff[lane];
            gate[m * SD + lane] = 1.0f / (1.0f + expf(-logit));
        } else if (lane < 16) {
            si[m * SD + (lane - 8)] = acc[r][lane] + b_in[EE + (lane - 8)];
        }
    }
}

// ---------------- parallel linear-recurrence scan ----------------
__global__ __launch_bounds__(128)
void scan_par_kernel(const float* __restrict__ gate,
                     const float* __restrict__ si,
                     float* __restrict__ states,
                     float* __restrict__ final_state)
{
    const int chain = blockIdx.x;            // 0..63
    const int b = chain >> 3, d = chain & 7;
    const int t = threadIdx.x;               // 0..127
    const int lane = t & 31, warp = t >> 5;
    const float* gp = gate + (size_t)b * SS * SD + d;
    const float* sp = si   + (size_t)b * SS * SD + d;
    float*       op = states + (size_t)b * SS * SD + d;
    const int s0 = t * 32;

    float g[32], cc[32];
    float G = 1.f, C = 0.f;
    #pragma unroll
    for (int u = 0; u < 32; u++) {
        float gv = gp[(s0 + u) * SD];
        float sv = sp[(s0 + u) * SD];
        float cv = sv - gv * sv;
        g[u] = gv; cc[u] = cv;
        C = fmaf(gv, C, cv);
        G = gv * G;
    }
    #pragma unroll
    for (int off = 1; off < 32; off <<= 1) {
        float pG = __shfl_up_sync(0xffffffffu, G, off);
        float pC = __shfl_up_sync(0xffffffffu, C, off);
        if (lane >= off) { C = fmaf(G, pC, C); G *= pG; }
    }
    __shared__ float wG[4], wC[4];
    if (lane == 31) { wG[warp] = G; wC[warp] = C; }
    __syncthreads();
    float preC = 0.f;
    for (int w = 0; w < warp; w++) { preC = fmaf(wG[w], preC, wC[w]); }
    float eG = __shfl_up_sync(0xffffffffu, G, 1);
    float eC = __shfl_up_sync(0xffffffffu, C, 1);
    if (lane == 0) { eG = 1.f; eC = 0.f; }
    float s = fmaf(eG, preC, eC);
    #pragma unroll
    for (int u = 0; u < 32; u++) {
        s = fmaf(g[u], s, cc[u]);
        op[(s0 + u) * SD] = s;
    }
    if (t == 127) final_state[b * SD + d] = s;
}

// ---------------- launch ----------------
extern "C" void kernel_launch(void* const* d_in, const int* in_sizes, int n_in,
                              void* d_out, int out_size)
{
    const float* x     = (const float*)d_in[0];
    const float* W_in  = (const float*)d_in[1];
    const float* b_in  = (const float*)d_in[2];
    const float* W_g   = (const float*)d_in[3];
    const float* b_g   = (const float*)d_in[4];
    const float* W_out = (const float*)d_in[5];
    const float* b_out = (const float*)d_in[6];
    float* out = (float*)d_out;

    float *Weff, *Wg_eff, *bg_eff, *bout_eff, *gate, *si, *states;
    __nv_bfloat16 *XHi, *XLo, *WinHi, *WinLo, *WoutHi, *WoutLo, *BweffHi, *BweffLo;
    cudaGetSymbolAddress((void**)&Weff,     g_Weff);
    cudaGetSymbolAddress((void**)&Wg_eff,   g_Wg_eff);
    cudaGetSymbolAddress((void**)&bg_eff,   g_bg_eff);
    cudaGetSymbolAddress((void**)&bout_eff, g_bout_eff);
    cudaGetSymbolAddress((void**)&gate,     g_gate);
    cudaGetSymbolAddress((void**)&si,       g_si);
    cudaGetSymbolAddress((void**)&states,   g_states);
    cudaGetSymbolAddress((void**)&XHi,      g_XHi);
    cudaGetSymbolAddress((void**)&XLo,      g_XLo);
    cudaGetSymbolAddress((void**)&WinHi,    g_WinHi);
    cudaGetSymbolAddress((void**)&WinLo,    g_WinLo);
    cudaGetSymbolAddress((void**)&WoutHi,   g_WoutHi);
    cudaGetSymbolAddress((void**)&WoutLo,   g_WoutLo);
    cudaGetSymbolAddress((void**)&BweffHi,  g_BweffHi);
    cudaGetSymbolAddress((void**)&BweffLo,  g_BweffLo);

    cudaFuncSetAttribute(gemm_mma_kernel,
                         cudaFuncAttributeMaxDynamicSharedMemorySize, 98304);

    // 1) small folded weights
    int tot = EE * SD + SD + EE;
    precompute_kernel<<<(tot + 255) / 256, 256>>>(W_in, W_g, b_g, b_in, W_out, b_out,
                                                  Wg_eff, bg_eff, bout_eff);

    // 2) decompose W_in top-square (rows) + W_out top-square (transposed)
    decompose_rows_kernel<<<EE, 256>>>(W_in, LDIN, WinHi, WinLo);
    decompose_trans_kernel<<<dim3(32, 32), dim3(32, 8)>>>(W_out, WoutHi, WoutLo);

    // 3) Weff = W_in[:, :E] @ W_out[:E, :]
    gemm_mma_kernel<<<dim3(8, 8), 256, 98304>>>(
        WinHi, WinLo, WoutHi, WoutLo, Weff, nullptr, nullptr, nullptr);

    // 4) decompose Weff (transposed) + x (rows)
    decompose_trans_kernel<<<dim3(32, 32), dim3(32, 8)>>>(Weff, BweffHi, BweffLo);
    decompose_rows_kernel<<<MM, 256>>>(x, EE, XHi, XLo);

    // 5) gate + state_in
    gate_si_kernel<<<MM / 32, 256>>>(x, Wg_eff, W_in, bg_eff, b_in, gate, si);

    // 6) parallel scan (also writes final_state at tail of output)
    scan_par_kernel<<<64, 128>>>(gate, si, states, out + (size_t)MM * EE);

    // 7) out = x @ Weff + states @ W_out[E:, :] + bout_eff
    gemm_mma_kernel<<<dim3(8, MM / 128), 256, 98304>>>(
        XHi, XLo, BweffHi, BweffLo, out, bout_eff, states, W_out + (size_t)EE * EE);
}

// round 7
// speedup vs baseline: 1.3925x; 1.3925x over previous
#include <cuda_runtime.h>
#include <cuda_fp16.h>
#include <math.h>
#include <stdint.h>

// ---------------- problem constants ----------------
#define BB 8
#define SS 4096
#define EE 1024
#define SD 8
#define MM (BB*SS)          // 32768
#define LDIN 1032           // E + SD
#define NITER 16            // K=1024 / 64

// ================= portable PTX helpers (sm_80+) =================
__device__ __forceinline__ uint32_t smem_to_u32(const void* smem_ptr) {
    uint32_t addr;
    asm("{ .reg .u64 tmp; cvta.to.shared.u64 tmp, %1; cvt.u32.u64 %0, tmp; }"
        : "=r"(addr) : "l"(smem_ptr));
    return addr;
}

#define CP_ASYNC16(dst, src) \
    asm volatile("cp.async.cg.shared.global [%0], [%1], 16;" \
                 :: "r"(dst), "l"(src) : "memory")
#define CP_COMMIT() asm volatile("cp.async.commit_group;" ::: "memory")
#define CP_WAIT1()  asm volatile("cp.async.wait_group 1;"  ::: "memory")

__device__ __forceinline__ void ldsm_x4(uint32_t& r0, uint32_t& r1,
                                        uint32_t& r2, uint32_t& r3,
                                        uint32_t addr) {
    asm volatile("ldmatrix.sync.aligned.m8n8.x4.shared.b16 {%0,%1,%2,%3}, [%4];"
                 : "=r"(r0), "=r"(r1), "=r"(r2), "=r"(r3) : "r"(addr));
}

__device__ __forceinline__ void mma16816(float* d, const uint32_t* a,
                                         const uint32_t* b) {
    asm volatile("mma.sync.aligned.m16n8k16.row.col.f32.f16.f16.f32 "
                 "{%0,%1,%2,%3}, {%4,%5,%6,%7}, {%8,%9}, {%0,%1,%2,%3};"
                 : "+f"(d[0]), "+f"(d[1]), "+f"(d[2]), "+f"(d[3])
                 : "r"(a[0]), "r"(a[1]), "r"(a[2]), "r"(a[3]),
                   "r"(b[0]), "r"(b[1]));
}

// ---------------- scratch (device globals, no allocs) ----------------
__device__ float g_Weff[EE * EE];
__device__ float g_Wg_eff[EE * SD];
__device__ float g_bg_eff[SD];
__device__ float g_bout_eff[EE];
__device__ float g_gate[MM * SD];
__device__ float g_si[MM * SD];
__device__ float g_states[MM * SD];
__device__ __half g_XHi[(size_t)MM * EE];      // 64 MB, x as fp16
__device__ __half g_WinHi[(size_t)EE * EE];    // 32*W_in top square, hi
__device__ __half g_WinLo[(size_t)EE * EE];
__device__ __half g_WoutHi[(size_t)EE * EE];   // 32*W_out top, transposed
__device__ __half g_WoutLo[(size_t)EE * EE];
__device__ __half g_BweffHi[(size_t)EE * EE];  // 32*Weff, transposed
__device__ __half g_BweffLo[(size_t)EE * EE];

// ---------------- precompute small folded weights ----------------
__global__ void precompute_kernel(const float* __restrict__ W_in,
                                  const float* __restrict__ W_g,
                                  const float* __restrict__ b_g,
                                  const float* __restrict__ b_in,
                                  const float* __restrict__ W_out,
                                  const float* __restrict__ b_out,
                                  float* __restrict__ Wg_eff,
                                  float* __restrict__ bg_eff,
                                  float* __restrict__ bout_eff)
{
    int gid = blockIdx.x * blockDim.x + threadIdx.x;
    if (gid < EE * SD) {
        int e = gid >> 3, d = gid & 7;
        float s = 0.f;
        const float* wr = W_in + (size_t)e * LDIN;
        #pragma unroll 4
        for (int c = 0; c < LDIN; c++) s = fmaf(wr[c], W_g[c * SD + d], s);
        Wg_eff[e * SD + d] = s;
    } else if (gid < EE * SD + SD) {
        int d = gid - EE * SD;
        float s = b_g[d];
        for (int c = 0; c < LDIN; c++) s = fmaf(b_in[c], W_g[c * SD + d], s);
        bg_eff[d] = s;
    } else if (gid < EE * SD + SD + EE) {
        int n = gid - (EE * SD + SD);
        float s = b_out[n];
        for (int c = 0; c < EE; c++) s = fmaf(b_in[c], W_out[(size_t)c * EE + n], s);
        bout_eff[n] = s;
    }
}

// ---------------- x -> fp16 cast (rows, scale 1, hi only) ----------------
__global__ void cast_f16_kernel(const float* __restrict__ src,
                                __half* __restrict__ dst)
{
    size_t i = ((size_t)blockIdx.x * 256 + threadIdx.x) * 4;
    float4 v = *(const float4*)(src + i);
    struct alignas(8) H4 { __half h[4]; };
    H4 o;
    o.h[0] = __float2half(v.x); o.h[1] = __float2half(v.y);
    o.h[2] = __float2half(v.z); o.h[3] = __float2half(v.w);
    *(H4*)(dst + i) = o;
}

// ---------------- hi/lo fp16 decomposition with scale, row-major ----------
__global__ void decompose_rows_f16(const float* __restrict__ src, int srcld,
                                   float scale,
                                   __half* __restrict__ Hi,
                                   __half* __restrict__ Lo)
{
    int r = blockIdx.x;
    int c4 = threadIdx.x * 4;
    float4 v = *(const float4*)(src + (size_t)r * srcld + c4);
    struct alignas(8) H4 { __half h[4]; };
    H4 H, L;
    float vv[4] = {v.x, v.y, v.z, v.w};
    #pragma unroll
    for (int i = 0; i < 4; i++) {
        float sv = vv[i] * scale;
        __half h = __float2half(sv);
        H.h[i] = h;
        L.h[i] = __float2half(sv - __half2float(h));
    }
    *(H4*)(Hi + (size_t)r * EE + c4) = H;
    *(H4*)(Lo + (size_t)r * EE + c4) = L;
}

// ---------------- hi/lo fp16 decomposition with scale, transposed ---------
__global__ void decompose_trans_f16(const float* __restrict__ src,
                                    float scale,
                                    __half* __restrict__ Hi,
                                    __half* __restrict__ Lo)
{
    __shared__ float tile[32][33];
    int e0 = blockIdx.x * 32, n0 = blockIdx.y * 32;
    int tx = threadIdx.x, ty = threadIdx.y;     // 32 x 8
    #pragma unroll
    for (int i = 0; i < 4; i++)
        tile[ty + i * 8][tx] = src[(size_t)(e0 + ty + i * 8) * 1024 + n0 + tx];
    __syncthreads();
    #pragma unroll
    for (int i = 0; i < 4; i++) {
        int n = n0 + ty + i * 8;
        float v = tile[tx][ty + i * 8] * scale;
        __half h = __float2half(v);
        __half l = __float2half(v - __half2float(h));
        Hi[(size_t)n * EE + e0 + tx] = h;
        Lo[(size_t)n * EE + e0 + tx] = l;
    }
}

// ================= warp-mma fp16 GEMM =================
// C[m][n] = osc * sum_k A[m][k]*B[n][k]  (+ optional epilogue).
// SPLIT_A=false: A = Ahi only (2 mma passes: A*Bhi + A*Blo).
// SPLIT_A=true : A = Ahi+Alo (3 passes: hi*hi + hi*lo + lo*hi).
// CTA 128x128, K-chunk 64, double-buffered cp.async, 8 warps (64x32 tiles).
// Sub-tiles per stage (16KB each, 128 rows x 64 fp16, swizzled 128B rows):
//   A @ +0, Bhi @ +16K, Blo @ +32K, [Alo @ +48K].
template<bool SPLIT_A>
__global__ void __launch_bounds__(256, 2)
gemm_f16_kernel(const __half* __restrict__ Ahi,
                const __half* __restrict__ Alo,
                const __half* __restrict__ Bhi,
                const __half* __restrict__ Blo,
                float* __restrict__ C, float osc,
                const float* __restrict__ bias,
                const float* __restrict__ Srank,
                const float* __restrict__ Wbot)
{
    constexpr uint32_t STAGE = SPLIT_A ? 65536u : 49152u;
    extern __shared__ char smem[];
    const uint32_t sb = smem_to_u32(smem);
    const int tid  = threadIdx.x;
    const int lane = tid & 31;
    const int wid  = tid >> 5;
    const int wm   = wid >> 2;                   // 0..1
    const int wn   = wid & 3;                    // 0..3
    const int n0   = blockIdx.x * 128;
    const int m0   = blockIdx.y * 128;

    float acc[4][4][4];
    #pragma unroll
    for (int mi = 0; mi < 4; mi++)
        #pragma unroll
        for (int ni = 0; ni < 4; ni++)
            #pragma unroll
            for (int e = 0; e < 4; e++) acc[mi][ni][e] = 0.f;

    const int row0 = tid >> 3;     // 0..31
    const int seg  = tid & 7;      // 16B segment

    auto prefetch = [&](int buf, int kb) {
        const uint32_t st = sb + (uint32_t)buf * STAGE;
        #pragma unroll
        for (int i = 0; i < 4; i++) {
            int row = row0 + i * 32;
            uint32_t sw = (uint32_t)row * 128u + (uint32_t)((seg ^ (row & 7)) * 16);
            CP_ASYNC16(st + sw,           Ahi + (size_t)(m0 + row) * EE + kb + seg * 8);
            CP_ASYNC16(st + 16384u + sw,  Bhi + (size_t)(n0 + row) * EE + kb + seg * 8);
            CP_ASYNC16(st + 32768u + sw,  Blo + (size_t)(n0 + row) * EE + kb + seg * 8);
            if (SPLIT_A)
                CP_ASYNC16(st + 49152u + sw, Alo + (size_t)(m0 + row) * EE + kb + seg * 8);
        }
    };

    prefetch(0, 0);
    CP_COMMIT();

    // ldmatrix per-thread row offsets (proven layout)
    const int rA  = ((lane >> 3) & 1) * 8 + (lane & 7);
    const int kA8 = lane >> 4;
    const int rB  = (lane >> 4) * 8 + (lane & 7);
    const int kB8 = (lane >> 3) & 1;

    for (int it = 0; it < NITER; it++) {
        if (it + 1 < NITER) prefetch((it + 1) & 1, (it + 1) * 64);
        CP_COMMIT();
        CP_WAIT1();
        __syncthreads();

        const uint32_t aB = sb + (uint32_t)(it & 1) * STAGE;

        #pragma unroll
        for (int ks = 0; ks < 4; ks++) {
            uint32_t af[4][4], afl[4][4], bh[4][2], bl[4][2];
            #pragma unroll
            for (int mi = 0; mi < 4; mi++) {
                int row = wm * 64 + mi * 16 + rA;
                int sh  = ks * 2 + kA8;
                uint32_t roff = (uint32_t)row * 128u + (uint32_t)((sh ^ (row & 7)) * 16);
                ldsm_x4(af[mi][0], af[mi][1], af[mi][2], af[mi][3], aB + roff);
                if (SPLIT_A)
                    ldsm_x4(afl[mi][0], afl[mi][1], afl[mi][2], afl[mi][3],
                            aB + 49152u + roff);
            }
            #pragma unroll
            for (int np = 0; np < 2; np++) {
                int row = wn * 32 + np * 16 + rB;
                int sh  = ks * 2 + kB8;
                uint32_t roff = (uint32_t)row * 128u + (uint32_t)((sh ^ (row & 7)) * 16);
                uint32_t r0, r1, r2, r3;
                ldsm_x4(r0, r1, r2, r3, aB + 16384u + roff);
                bh[np * 2][0] = r0;     bh[np * 2][1] = r1;
                bh[np * 2 + 1][0] = r2; bh[np * 2 + 1][1] = r3;
                ldsm_x4(r0, r1, r2, r3, aB + 32768u + roff);
                bl[np * 2][0] = r0;     bl[np * 2][1] = r1;
                bl[np * 2 + 1][0] = r2; bl[np * 2 + 1][1] = r3;
            }
            #pragma unroll
            for (int mi = 0; mi < 4; mi++)
                #pragma unroll
                for (int ni = 0; ni < 4; ni++) {
                    mma16816(acc[mi][ni], af[mi], bh[ni]);        // hi·hi
                    mma16816(acc[mi][ni], af[mi], bl[ni]);        // hi·lo
                    if (SPLIT_A)
                        mma16816(acc[mi][ni], afl[mi], bh[ni]);   // lo·hi
                }
        }
        __syncthreads();
    }

    // ---------------- epilogue ----------------
    const bool epi = (Srank != nullptr);
    float* const sBias = (float*)smem;                 // 128 f
    float* const sSt   = (float*)(smem + 512);         // 128 x 8
    float* const sWb   = (float*)(smem + 512 + 4096);  // 8 x 128
    if (epi) {
        if (tid < 128) sBias[tid] = bias[n0 + tid];
        ((float4*)sSt)[tid] = ((const float4*)(Srank + (size_t)m0 * SD))[tid];
        for (int i = tid; i < 1024; i += 256) {
            int d8 = i >> 7, nl = i & 127;
            sWb[d8 * 128 + nl] = Wbot[(size_t)d8 * 1024 + n0 + nl];
        }
    }
    __syncthreads();

    const int lr  = lane >> 2;
    const int lc2 = (lane & 3) * 2;
    #pragma unroll
    for (int mi = 0; mi < 4; mi++) {
        int r0l = wm * 64 + mi * 16 + lr;
        int r1l = r0l + 8;
        float st0[SD], st1[SD];
        if (epi) {
            #pragma unroll
            for (int d = 0; d < SD; d++) {
                st0[d] = sSt[r0l * SD + d];
                st1[d] = sSt[r1l * SD + d];
            }
        }
        #pragma unroll
        for (int ni = 0; ni < 4; ni++) {
            int cg = wn * 32 + ni * 8 + lc2;
            float* d = acc[mi][ni];
            float v0 = d[0] * osc, v1 = d[1] * osc;
            float v2 = d[2] * osc, v3 = d[3] * osc;
            if (epi) {
                float s00 = sBias[cg], s01 = sBias[cg + 1];
                float s10 = s00, s11 = s01;
                #pragma unroll
                for (int dd = 0; dd < SD; dd++) {
                    float w0 = sWb[dd * 128 + cg], w1 = sWb[dd * 128 + cg + 1];
                    s00 = fmaf(st0[dd], w0, s00); s01 = fmaf(st0[dd], w1, s01);
                    s10 = fmaf(st1[dd], w0, s10); s11 = fmaf(st1[dd], w1, s11);
                }
                v0 += s00; v1 += s01; v2 += s10; v3 += s11;
            }
            float2 o0 = { v0, v1 };
            float2 o1 = { v2, v3 };
            *(float2*)(C + (size_t)(m0 + r0l) * 1024 + n0 + cg) = o0;
            *(float2*)(C + (size_t)(m0 + r1l) * 1024 + n0 + cg) = o1;
        }
    }
}

// ---------------- skinny pass: gate + state_in ----------------
__global__ __launch_bounds__(256)
void gate_si_kernel(const float* __restrict__ x,
                    const float* __restrict__ Wg_eff,
                    const float* __restrict__ W_in,
                    const float* __restrict__ bg_eff,
                    const float* __restrict__ b_in,
                    float* __restrict__ gate,
                    float* __restrict__ si)
{
    __shared__ float sWT[16][512];
    const int tid = threadIdx.x;
    const int lane = tid & 31;
    const int warp = tid >> 5;
    const int m0 = blockIdx.x * 32 + warp * 4;

    float acc[4][16];
    #pragma unroll
    for (int r = 0; r < 4; r++)
        #pragma unroll
        for (int d = 0; d < 16; d++) acc[r][d] = 0.f;

    for (int p = 0; p < 2; p++) {
        for (int idx = tid; idx < 16 * 512; idx += 256) {
            int d = idx >> 9, el = idx & 511;
            int e = p * 512 + el;
            sWT[d][el] = (d < 8) ? Wg_eff[e * SD + d]
                                 : W_in[(size_t)e * LDIN + EE + (d - 8)];
        }
        __syncthreads();

        for (int eb = 0; eb < 512; eb += 32) {
            float xv[4];
            #pragma unroll
            for (int r = 0; r < 4; r++)
                xv[r] = x[(size_t)(m0 + r) * EE + p * 512 + eb + lane];
            #pragma unroll
            for (int d = 0; d < 16; d++) {
                float w = sWT[d][eb + lane];
                #pragma unroll
                for (int r = 0; r < 4; r++)
                    acc[r][d] = fmaf(xv[r], w, acc[r][d]);
            }
        }
        __syncthreads();
    }

    #pragma unroll
    for (int r = 0; r < 4; r++) {
        #pragma unroll
        for (int d = 0; d < 16; d++) {
            float v = acc[r][d];
            v += __shfl_xor_sync(0xffffffffu, v, 16);
            v += __shfl_xor_sync(0xffffffffu, v, 8);
            v += __shfl_xor_sync(0xffffffffu, v, 4);
            v += __shfl_xor_sync(0xffffffffu, v, 2);
            v += __shfl_xor_sync(0xffffffffu, v, 1);
            acc[r][d] = v;
        }
        int m = m0 + r;
        if (lane < 8) {
            float logit = acc[r][lane] + bg_eff[lane];
            gate[m * SD + lane] = 1.0f / (1.0f + expf(-logit));
        } else if (lane < 16) {
            si[m * SD + (lane - 8)] = acc[r][lane] + b_in[EE + (lane - 8)];
        }
    }
}

// ---------------- parallel linear-recurrence scan ----------------
__global__ __launch_bounds__(128)
void scan_par_kernel(const float* __restrict__ gate,
                     const float* __restrict__ si,
                     float* __restrict__ states,
                     float* __restrict__ final_state)
{
    const int chain = blockIdx.x;            // 0..63
    const int b = chain >> 3, d = chain & 7;
    const int t = threadIdx.x;               // 0..127
    const int lane = t & 31, warp = t >> 5;
    const float* gp = gate + (size_t)b * SS * SD + d;
    const float* sp = si   + (size_t)b * SS * SD + d;
    float*       op = states + (size_t)b * SS * SD + d;
    const int s0 = t * 32;

    float g[32], cc[32];
    float G = 1.f, C = 0.f;
    #pragma unroll
    for (int u = 0; u < 32; u++) {
        float gv = gp[(s0 + u) * SD];
        float sv = sp[(s0 + u) * SD];
        float cv = sv - gv * sv;
        g[u] = gv; cc[u] = cv;
        C = fmaf(gv, C, cv);
        G = gv * G;
    }
    #pragma unroll
    for (int off = 1; off < 32; off <<= 1) {
        float pG = __shfl_up_sync(0xffffffffu, G, off);
        float pC = __shfl_up_sync(0xffffffffu, C, off);
        if (lane >= off) { C = fmaf(G, pC, C); G *= pG; }
    }
    __shared__ float wG[4], wC[4];
    if (lane == 31) { wG[warp] = G; wC[warp] = C; }
    __syncthreads();
    float preC = 0.f;
    for (int w = 0; w < warp; w++) { preC = fmaf(wG[w], preC, wC[w]); }
    float eG = __shfl_up_sync(0xffffffffu, G, 1);
    float eC = __shfl_up_sync(0xffffffffu, C, 1);
    if (lane == 0) { eG = 1.f; eC = 0.f; }
    float s = fmaf(eG, preC, eC);
    #pragma unroll
    for (int u = 0; u < 32; u++) {
        s = fmaf(g[u], s, cc[u]);
        op[(s0 + u) * SD] = s;
    }
    if (t == 127) final_state[b * SD + d] = s;
}

// ---------------- launch ----------------
extern "C" void kernel_launch(void* const* d_in, const int* in_sizes, int n_in,
                              void* d_out, int out_size)
{
    const float* x     = (const float*)d_in[0];
    const float* W_in  = (const float*)d_in[1];
    const float* b_in  = (const float*)d_in[2];
    const float* W_g   = (const float*)d_in[3];
    const float* b_g   = (const float*)d_in[4];
    const float* W_out = (const float*)d_in[5];
    const float* b_out = (const float*)d_in[6];
    float* out = (float*)d_out;

    float *Weff, *Wg_eff, *bg_eff, *bout_eff, *gate, *si, *states;
    __half *XHi, *WinHi, *WinLo, *WoutHi, *WoutLo, *BweffHi, *BweffLo;
    cudaGetSymbolAddress((void**)&Weff,     g_Weff);
    cudaGetSymbolAddress((void**)&Wg_eff,   g_Wg_eff);
    cudaGetSymbolAddress((void**)&bg_eff,   g_bg_eff);
    cudaGetSymbolAddress((void**)&bout_eff, g_bout_eff);
    cudaGetSymbolAddress((void**)&gate,     g_gate);
    cudaGetSymbolAddress((void**)&si,       g_si);
    cudaGetSymbolAddress((void**)&states,   g_states);
    cudaGetSymbolAddress((void**)&XHi,      g_XHi);
    cudaGetSymbolAddress((void**)&WinHi,    g_WinHi);
    cudaGetSymbolAddress((void**)&WinLo,    g_WinLo);
    cudaGetSymbolAddress((void**)&WoutHi,   g_WoutHi);
    cudaGetSymbolAddress((void**)&WoutLo,   g_WoutLo);
    cudaGetSymbolAddress((void**)&BweffHi,  g_BweffHi);
    cudaGetSymbolAddress((void**)&BweffLo,  g_BweffLo);

    cudaFuncSetAttribute(gemm_f16_kernel<false>,
                         cudaFuncAttributeMaxDynamicSharedMemorySize, 98304);
    cudaFuncSetAttribute(gemm_f16_kernel<true>,
                         cudaFuncAttributeMaxDynamicSharedMemorySize, 131072);

    // 1) small folded weights
    int tot = EE * SD + SD + EE;
    precompute_kernel<<<(tot + 255) / 256, 256>>>(W_in, W_g, b_g, b_in, W_out, b_out,
                                                  Wg_eff, bg_eff, bout_eff);

    // 2) decompose 32*W_in top-square (rows) + 32*W_out top (transposed)
    decompose_rows_f16<<<EE, 256>>>(W_in, LDIN, 32.0f, WinHi, WinLo);
    decompose_trans_f16<<<dim3(32, 32), dim3(32, 8)>>>(W_out, 32.0f, WoutHi, WoutLo);

    // 3) Weff = W_in[:, :E] @ W_out[:E, :]  (3-term, accurate; /1024 undoes 32*32)
    gemm_f16_kernel<true><<<dim3(8, 8), 256, 131072>>>(
        WinHi, WinLo, WoutHi, WoutLo, Weff, 1.0f / 1024.0f,
        nullptr, nullptr, nullptr);

    // 4) decompose 32*Weff (transposed) + cast x to fp16
    decompose_trans_f16<<<dim3(32, 32), dim3(32, 8)>>>(Weff, 32.0f, BweffHi, BweffLo);
    cast_f16_kernel<<<MM * EE / 1024, 256>>>(x, XHi);

    // 5) gate + state_in (fp32-exact path)
    gate_si_kernel<<<MM / 32, 256>>>(x, Wg_eff, W_in, bg_eff, b_in, gate, si);

    // 6) parallel scan (also writes final_state at tail of output)
    scan_par_kernel<<<64, 128>>>(gate, si, states, out + (size_t)MM * EE);

    // 7) out = x @ Weff + states @ W_out[E:, :] + bout_eff   (2-term, /32)
    gemm_f16_kernel<false><<<dim3(8, MM / 128), 256, 98304>>>(
        XHi, nullptr, BweffHi, BweffLo, out, 1.0f / 32.0f,
        bout_eff, states, W_out + (size_t)EE * EE);
}

// round 8
// speedup vs baseline: 1.8132x; 1.3020x over previous
#include <cuda_runtime.h>
#include <cuda_fp16.h>
#include <math.h>
#include <stdint.h>

// ---------------- problem constants ----------------
#define BB 8
#define SS 4096
#define EE 1024
#define SD 8
#define MM (BB*SS)          // 32768
#define LDIN 1032           // E + SD
#define NITER 16            // K=1024 / 64

// ================= portable PTX helpers (sm_80+) =================
__device__ __forceinline__ uint32_t smem_to_u32(const void* smem_ptr) {
    uint32_t addr;
    asm("{ .reg .u64 tmp; cvta.to.shared.u64 tmp, %1; cvt.u32.u64 %0, tmp; }"
        : "=r"(addr) : "l"(smem_ptr));
    return addr;
}

#define CP_ASYNC16(dst, src) \
    asm volatile("cp.async.cg.shared.global [%0], [%1], 16;" \
                 :: "r"(dst), "l"(src) : "memory")
#define CP_COMMIT() asm volatile("cp.async.commit_group;" ::: "memory")
#define CP_WAIT1()  asm volatile("cp.async.wait_group 1;"  ::: "memory")

__device__ __forceinline__ void ldsm_x4(uint32_t& r0, uint32_t& r1,
                                        uint32_t& r2, uint32_t& r3,
                                        uint32_t addr) {
    asm volatile("ldmatrix.sync.aligned.m8n8.x4.shared.b16 {%0,%1,%2,%3}, [%4];"
                 : "=r"(r0), "=r"(r1), "=r"(r2), "=r"(r3) : "r"(addr));
}

__device__ __forceinline__ void mma16816(float* d, const uint32_t* a,
                                         const uint32_t* b) {
    asm volatile("mma.sync.aligned.m16n8k16.row.col.f32.f16.f16.f32 "
                 "{%0,%1,%2,%3}, {%4,%5,%6,%7}, {%8,%9}, {%0,%1,%2,%3};"
                 : "+f"(d[0]), "+f"(d[1]), "+f"(d[2]), "+f"(d[3])
                 : "r"(a[0]), "r"(a[1]), "r"(a[2]), "r"(a[3]),
                   "r"(b[0]), "r"(b[1]));
}

// ---------------- scratch (device globals, no allocs) ----------------
__device__ float g_Weff[EE * EE];
__device__ float g_Wg_eff[EE * SD];
__device__ float g_bg_eff[SD];
__device__ float g_bout_eff[EE];
__device__ float g_gate[MM * SD];
__device__ float g_si[MM * SD];
__device__ float g_states[MM * SD];
__device__ __half g_XHi[(size_t)MM * EE];      // 64 MB, x as fp16 (written by gate_si)
__device__ __half g_WinHi[(size_t)EE * EE];    // 32*W_in top square, hi
__device__ __half g_WinLo[(size_t)EE * EE];
__device__ __half g_WoutHi[(size_t)EE * EE];   // 32*W_out top, transposed
__device__ __half g_WoutLo[(size_t)EE * EE];
__device__ __half g_BweffH[(size_t)EE * EE];   // Weff fp16, transposed, single

// ---------------- precompute small folded weights ----------------
__global__ void precompute_kernel(const float* __restrict__ W_in,
                                  const float* __restrict__ W_g,
                                  const float* __restrict__ b_g,
                                  const float* __restrict__ b_in,
                                  const float* __restrict__ W_out,
                                  const float* __restrict__ b_out,
                                  float* __restrict__ Wg_eff,
                                  float* __restrict__ bg_eff,
                                  float* __restrict__ bout_eff)
{
    int gid = blockIdx.x * blockDim.x + threadIdx.x;
    if (gid < EE * SD) {
        int e = gid >> 3, d = gid & 7;
        float s = 0.f;
        const float* wr = W_in + (size_t)e * LDIN;
        #pragma unroll 4
        for (int c = 0; c < LDIN; c++) s = fmaf(wr[c], W_g[c * SD + d], s);
        Wg_eff[e * SD + d] = s;
    } else if (gid < EE * SD + SD) {
        int d = gid - EE * SD;
        float s = b_g[d];
        for (int c = 0; c < LDIN; c++) s = fmaf(b_in[c], W_g[c * SD + d], s);
        bg_eff[d] = s;
    } else if (gid < EE * SD + SD + EE) {
        int n = gid - (EE * SD + SD);
        float s = b_out[n];
        for (int c = 0; c < EE; c++) s = fmaf(b_in[c], W_out[(size_t)c * EE + n], s);
        bout_eff[n] = s;
    }
}

// ---------------- hi/lo fp16 decomposition with scale, row-major ----------
__global__ void decompose_rows_f16(const float* __restrict__ src, int srcld,
                                   float scale,
                                   __half* __restrict__ Hi,
                                   __half* __restrict__ Lo)
{
    int r = blockIdx.x;
    int c4 = threadIdx.x * 4;
    float4 v = *(const float4*)(src + (size_t)r * srcld + c4);
    struct alignas(8) H4 { __half h[4]; };
    H4 H, L;
    float vv[4] = {v.x, v.y, v.z, v.w};
    #pragma unroll
    for (int i = 0; i < 4; i++) {
        float sv = vv[i] * scale;
        __half h = __float2half(sv);
        H.h[i] = h;
        L.h[i] = __float2half(sv - __half2float(h));
    }
    *(H4*)(Hi + (size_t)r * EE + c4) = H;
    *(H4*)(Lo + (size_t)r * EE + c4) = L;
}

// ---------------- hi/lo fp16 decomposition with scale, transposed ---------
__global__ void decompose_trans_f16(const float* __restrict__ src,
                                    float scale,
                                    __half* __restrict__ Hi,
                                    __half* __restrict__ Lo)
{
    __shared__ float tile[32][33];
    int e0 = blockIdx.x * 32, n0 = blockIdx.y * 32;
    int tx = threadIdx.x, ty = threadIdx.y;     // 32 x 8
    #pragma unroll
    for (int i = 0; i < 4; i++)
        tile[ty + i * 8][tx] = src[(size_t)(e0 + ty + i * 8) * 1024 + n0 + tx];
    __syncthreads();
    #pragma unroll
    for (int i = 0; i < 4; i++) {
        int n = n0 + ty + i * 8;
        float v = tile[tx][ty + i * 8] * scale;
        __half h = __float2half(v);
        Hi[(size_t)n * EE + e0 + tx] = h;
        if (Lo) Lo[(size_t)n * EE + e0 + tx] = __float2half(v - __half2float(h));
    }
}

// ================= warp-mma fp16 GEMM =================
// C[m][n] = osc * sum_k A[m][k]*B[n][k]  (+ optional epilogue).
// TERMS=1: single A x single B (1 mma pass).  Stage: A@0 16K, B@16K. 32KB.
// TERMS=3: A hi/lo, B hi/lo (hi*hi + hi*lo + lo*hi). Stage: A@0,Bhi@16K,Blo@32K,Alo@48K. 64KB.
// CTA 128x128, K-chunk 64, double-buffered cp.async, 8 warps (64x32 tiles).
template<int TERMS>
__global__ void __launch_bounds__(256, 2)
gemm_f16_kernel(const __half* __restrict__ Ahi,
                const __half* __restrict__ Alo,
                const __half* __restrict__ Bhi,
                const __half* __restrict__ Blo,
                float* __restrict__ C, float osc,
                const float* __restrict__ bias,
                const float* __restrict__ Srank,
                const float* __restrict__ Wbot)
{
    constexpr uint32_t STAGE = (TERMS == 3) ? 65536u : 32768u;
    extern __shared__ char smem[];
    const uint32_t sb = smem_to_u32(smem);
    const int tid  = threadIdx.x;
    const int lane = tid & 31;
    const int wid  = tid >> 5;
    const int wm   = wid >> 2;                   // 0..1
    const int wn   = wid & 3;                    // 0..3
    const int n0   = blockIdx.x * 128;
    const int m0   = blockIdx.y * 128;

    float acc[4][4][4];
    #pragma unroll
    for (int mi = 0; mi < 4; mi++)
        #pragma unroll
        for (int ni = 0; ni < 4; ni++)
            #pragma unroll
            for (int e = 0; e < 4; e++) acc[mi][ni][e] = 0.f;

    const int row0 = tid >> 3;     // 0..31
    const int seg  = tid & 7;      // 16B segment

    auto prefetch = [&](int buf, int kb) {
        const uint32_t st = sb + (uint32_t)buf * STAGE;
        #pragma unroll
        for (int i = 0; i < 4; i++) {
            int row = row0 + i * 32;
            uint32_t sw = (uint32_t)row * 128u + (uint32_t)((seg ^ (row & 7)) * 16);
            CP_ASYNC16(st + sw,          Ahi + (size_t)(m0 + row) * EE + kb + seg * 8);
            CP_ASYNC16(st + 16384u + sw, Bhi + (size_t)(n0 + row) * EE + kb + seg * 8);
            if (TERMS == 3) {
                CP_ASYNC16(st + 32768u + sw, Blo + (size_t)(n0 + row) * EE + kb + seg * 8);
                CP_ASYNC16(st + 49152u + sw, Alo + (size_t)(m0 + row) * EE + kb + seg * 8);
            }
        }
    };

    prefetch(0, 0);
    CP_COMMIT();

    // ldmatrix per-thread row offsets (proven layout)
    const int rA  = ((lane >> 3) & 1) * 8 + (lane & 7);
    const int kA8 = lane >> 4;
    const int rB  = (lane >> 4) * 8 + (lane & 7);
    const int kB8 = (lane >> 3) & 1;

    for (int it = 0; it < NITER; it++) {
        if (it + 1 < NITER) prefetch((it + 1) & 1, (it + 1) * 64);
        CP_COMMIT();
        CP_WAIT1();
        __syncthreads();

        const uint32_t aB = sb + (uint32_t)(it & 1) * STAGE;

        #pragma unroll
        for (int ks = 0; ks < 4; ks++) {
            uint32_t af[4][4], afl[4][4], bh[4][2], bl[4][2];
            #pragma unroll
            for (int mi = 0; mi < 4; mi++) {
                int row = wm * 64 + mi * 16 + rA;
                int sh  = ks * 2 + kA8;
                uint32_t roff = (uint32_t)row * 128u + (uint32_t)((sh ^ (row & 7)) * 16);
                ldsm_x4(af[mi][0], af[mi][1], af[mi][2], af[mi][3], aB + roff);
                if (TERMS == 3)
                    ldsm_x4(afl[mi][0], afl[mi][1], afl[mi][2], afl[mi][3],
                            aB + 49152u + roff);
            }
            #pragma unroll
            for (int np = 0; np < 2; np++) {
                int row = wn * 32 + np * 16 + rB;
                int sh  = ks * 2 + kB8;
                uint32_t roff = (uint32_t)row * 128u + (uint32_t)((sh ^ (row & 7)) * 16);
                uint32_t r0, r1, r2, r3;
                ldsm_x4(r0, r1, r2, r3, aB + 16384u + roff);
                bh[np * 2][0] = r0;     bh[np * 2][1] = r1;
                bh[np * 2 + 1][0] = r2; bh[np * 2 + 1][1] = r3;
                if (TERMS == 3) {
                    ldsm_x4(r0, r1, r2, r3, aB + 32768u + roff);
                    bl[np * 2][0] = r0;     bl[np * 2][1] = r1;
                    bl[np * 2 + 1][0] = r2; bl[np * 2 + 1][1] = r3;
                }
            }
            #pragma unroll
            for (int mi = 0; mi < 4; mi++)
                #pragma unroll
                for (int ni = 0; ni < 4; ni++) {
                    mma16816(acc[mi][ni], af[mi], bh[ni]);        // hi·hi
                    if (TERMS == 3) {
                        mma16816(acc[mi][ni], af[mi], bl[ni]);    // hi·lo
                        mma16816(acc[mi][ni], afl[mi], bh[ni]);   // lo·hi
                    }
                }
        }
        __syncthreads();
    }

    // ---------------- epilogue ----------------
    const bool epi = (Srank != nullptr);
    float* const sBias = (float*)smem;                 // 128 f
    float* const sSt   = (float*)(smem + 512);         // 128 x 8
    float* const sWb   = (float*)(smem + 512 + 4096);  // 8 x 128
    if (epi) {
        if (tid < 128) sBias[tid] = bias[n0 + tid];
        ((float4*)sSt)[tid] = ((const float4*)(Srank + (size_t)m0 * SD))[tid];
        for (int i = tid; i < 1024; i += 256) {
            int d8 = i >> 7, nl = i & 127;
            sWb[d8 * 128 + nl] = Wbot[(size_t)d8 * 1024 + n0 + nl];
        }
    }
    __syncthreads();

    const int lr  = lane >> 2;
    const int lc2 = (lane & 3) * 2;
    #pragma unroll
    for (int mi = 0; mi < 4; mi++) {
        int r0l = wm * 64 + mi * 16 + lr;
        int r1l = r0l + 8;
        float st0[SD], st1[SD];
        if (epi) {
            #pragma unroll
            for (int d = 0; d < SD; d++) {
                st0[d] = sSt[r0l * SD + d];
                st1[d] = sSt[r1l * SD + d];
            }
        }
        #pragma unroll
        for (int ni = 0; ni < 4; ni++) {
            int cg = wn * 32 + ni * 8 + lc2;
            float* d = acc[mi][ni];
            float v0 = d[0] * osc, v1 = d[1] * osc;
            float v2 = d[2] * osc, v3 = d[3] * osc;
            if (epi) {
                float s00 = sBias[cg], s01 = sBias[cg + 1];
                float s10 = s00, s11 = s01;
                #pragma unroll
                for (int dd = 0; dd < SD; dd++) {
                    float w0 = sWb[dd * 128 + cg], w1 = sWb[dd * 128 + cg + 1];
                    s00 = fmaf(st0[dd], w0, s00); s01 = fmaf(st0[dd], w1, s01);
                    s10 = fmaf(st1[dd], w0, s10); s11 = fmaf(st1[dd], w1, s11);
                }
                v0 += s00; v1 += s01; v2 += s10; v3 += s11;
            }
            float2 o0 = { v0, v1 };
            float2 o1 = { v2, v3 };
            *(float2*)(C + (size_t)(m0 + r0l) * 1024 + n0 + cg) = o0;
            *(float2*)(C + (size_t)(m0 + r1l) * 1024 + n0 + cg) = o1;
        }
    }
}

// ---------------- skinny pass: gate + state_in + x->fp16 cast -------------
__global__ __launch_bounds__(256)
void gate_si_kernel(const float* __restrict__ x,
                    const float* __restrict__ Wg_eff,
                    const float* __restrict__ W_in,
                    const float* __restrict__ bg_eff,
                    const float* __restrict__ b_in,
                    float* __restrict__ gate,
                    float* __restrict__ si,
                    __half* __restrict__ xh)
{
    __shared__ float sWT[16][512];
    const int tid = threadIdx.x;
    const int lane = tid & 31;
    const int warp = tid >> 5;
    const int m0 = blockIdx.x * 32 + warp * 4;

    float acc[4][16];
    #pragma unroll
    for (int r = 0; r < 4; r++)
        #pragma unroll
        for (int d = 0; d < 16; d++) acc[r][d] = 0.f;

    for (int p = 0; p < 2; p++) {
        for (int idx = tid; idx < 16 * 512; idx += 256) {
            int d = idx >> 9, el = idx & 511;
            int e = p * 512 + el;
            sWT[d][el] = (d < 8) ? Wg_eff[e * SD + d]
                                 : W_in[(size_t)e * LDIN + EE + (d - 8)];
        }
        __syncthreads();

        for (int eb = 0; eb < 512; eb += 32) {
            float xv[4];
            #pragma unroll
            for (int r = 0; r < 4; r++) {
                size_t xi = (size_t)(m0 + r) * EE + p * 512 + eb + lane;
                xv[r] = x[xi];
                xh[xi] = __float2half(xv[r]);      // fused fp16 cast
            }
            #pragma unroll
            for (int d = 0; d < 16; d++) {
                float w = sWT[d][eb + lane];
                #pragma unroll
                for (int r = 0; r < 4; r++)
                    acc[r][d] = fmaf(xv[r], w, acc[r][d]);
            }
        }
        __syncthreads();
    }

    #pragma unroll
    for (int r = 0; r < 4; r++) {
        #pragma unroll
        for (int d = 0; d < 16; d++) {
            float v = acc[r][d];
            v += __shfl_xor_sync(0xffffffffu, v, 16);
            v += __shfl_xor_sync(0xffffffffu, v, 8);
            v += __shfl_xor_sync(0xffffffffu, v, 4);
            v += __shfl_xor_sync(0xffffffffu, v, 2);
            v += __shfl_xor_sync(0xffffffffu, v, 1);
            acc[r][d] = v;
        }
        int m = m0 + r;
        if (lane < 8) {
            float logit = acc[r][lane] + bg_eff[lane];
            gate[m * SD + lane] = 1.0f / (1.0f + expf(-logit));
        } else if (lane < 16) {
            si[m * SD + (lane - 8)] = acc[r][lane] + b_in[EE + (lane - 8)];
        }
    }
}

// ---------------- parallel linear-recurrence scan ----------------
__global__ __launch_bounds__(128)
void scan_par_kernel(const float* __restrict__ gate,
                     const float* __restrict__ si,
                     float* __restrict__ states,
                     float* __restrict__ final_state)
{
    const int chain = blockIdx.x;            // 0..63
    const int b = chain >> 3, d = chain & 7;
    const int t = threadIdx.x;               // 0..127
    const int lane = t & 31, warp = t >> 5;
    const float* gp = gate + (size_t)b * SS * SD + d;
    const float* sp = si   + (size_t)b * SS * SD + d;
    float*       op = states + (size_t)b * SS * SD + d;
    const int s0 = t * 32;

    float g[32], cc[32];
    float G = 1.f, C = 0.f;
    #pragma unroll
    for (int u = 0; u < 32; u++) {
        float gv = gp[(s0 + u) * SD];
        float sv = sp[(s0 + u) * SD];
        float cv = sv - gv * sv;
        g[u] = gv; cc[u] = cv;
        C = fmaf(gv, C, cv);
        G = gv * G;
    }
    #pragma unroll
    for (int off = 1; off < 32; off <<= 1) {
        float pG = __shfl_up_sync(0xffffffffu, G, off);
        float pC = __shfl_up_sync(0xffffffffu, C, off);
        if (lane >= off) { C = fmaf(G, pC, C); G *= pG; }
    }
    __shared__ float wG[4], wC[4];
    if (lane == 31) { wG[warp] = G; wC[warp] = C; }
    __syncthreads();
    float preC = 0.f;
    for (int w = 0; w < warp; w++) { preC = fmaf(wG[w], preC, wC[w]); }
    float eG = __shfl_up_sync(0xffffffffu, G, 1);
    float eC = __shfl_up_sync(0xffffffffu, C, 1);
    if (lane == 0) { eG = 1.f; eC = 0.f; }
    float s = fmaf(eG, preC, eC);
    #pragma unroll
    for (int u = 0; u < 32; u++) {
        s = fmaf(g[u], s, cc[u]);
        op[(s0 + u) * SD] = s;
    }
    if (t == 127) final_state[b * SD + d] = s;
}

// ---------------- launch ----------------
extern "C" void kernel_launch(void* const* d_in, const int* in_sizes, int n_in,
                              void* d_out, int out_size)
{
    const float* x     = (const float*)d_in[0];
    const float* W_in  = (const float*)d_in[1];
    const float* b_in  = (const float*)d_in[2];
    const float* W_g   = (const float*)d_in[3];
    const float* b_g   = (const float*)d_in[4];
    const float* W_out = (const float*)d_in[5];
    const float* b_out = (const float*)d_in[6];
    float* out = (float*)d_out;

    float *Weff, *Wg_eff, *bg_eff, *bout_eff, *gate, *si, *states;
    __half *XHi, *WinHi, *WinLo, *WoutHi, *WoutLo, *BweffH;
    cudaGetSymbolAddress((void**)&Weff,     g_Weff);
    cudaGetSymbolAddress((void**)&Wg_eff,   g_Wg_eff);
    cudaGetSymbolAddress((void**)&bg_eff,   g_bg_eff);
    cudaGetSymbolAddress((void**)&bout_eff, g_bout_eff);
    cudaGetSymbolAddress((void**)&gate,     g_gate);
    cudaGetSymbolAddress((void**)&si,       g_si);
    cudaGetSymbolAddress((void**)&states,   g_states);
    cudaGetSymbolAddress((void**)&XHi,      g_XHi);
    cudaGetSymbolAddress((void**)&WinHi,    g_WinHi);
    cudaGetSymbolAddress((void**)&WinLo,    g_WinLo);
    cudaGetSymbolAddress((void**)&WoutHi,   g_WoutHi);
    cudaGetSymbolAddress((void**)&WoutLo,   g_WoutLo);
    cudaGetSymbolAddress((void**)&BweffH,   g_BweffH);

    cudaFuncSetAttribute(gemm_f16_kernel<1>,
                         cudaFuncAttributeMaxDynamicSharedMemorySize, 65536);
    cudaFuncSetAttribute(gemm_f16_kernel<3>,
                         cudaFuncAttributeMaxDynamicSharedMemorySize, 131072);

    // 1) small folded weights
    int tot = EE * SD + SD + EE;
    precompute_kernel<<<(tot + 255) / 256, 256>>>(W_in, W_g, b_g, b_in, W_out, b_out,
                                                  Wg_eff, bg_eff, bout_eff);

    // 2) decompose 32*W_in top-square (rows) + 32*W_out top (transposed), hi/lo
    decompose_rows_f16<<<EE, 256>>>(W_in, LDIN, 32.0f, WinHi, WinLo);
    decompose_trans_f16<<<dim3(32, 32), dim3(32, 8)>>>(W_out, 32.0f, WoutHi, WoutLo);

    // 3) Weff = W_in[:, :E] @ W_out[:E, :]  (3-term accurate; /1024 undoes 32*32)
    gemm_f16_kernel<3><<<dim3(8, 8), 256, 131072>>>(
        WinHi, WinLo, WoutHi, WoutLo, Weff, 1.0f / 1024.0f,
        nullptr, nullptr, nullptr);

    // 4) Weff -> single fp16, transposed
    decompose_trans_f16<<<dim3(32, 32), dim3(32, 8)>>>(Weff, 1.0f, BweffH, nullptr);

    // 5) gate + state_in + fused x->fp16 cast
    gate_si_kernel<<<MM / 32, 256>>>(x, Wg_eff, W_in, bg_eff, b_in, gate, si, XHi);

    // 6) parallel scan (also writes final_state at tail of output)
    scan_par_kernel<<<64, 128>>>(gate, si, states, out + (size_t)MM * EE);

    // 7) out = x @ Weff + states @ W_out[E:, :] + bout_eff   (1-term fp16)
    gemm_f16_kernel<1><<<dim3(8, MM / 128), 256, 65536>>>(
        XHi, nullptr, BweffH, nullptr, out, 1.0f,
        bout_eff, states, W_out + (size_t)EE * EE);
}